// round 1
// baseline (speedup 1.0000x reference)
#include <cuda_runtime.h>

#define S_LEN 2048
#define EMB   1024
#define BATCH 2
#define NH    16
#define DH    64

// Scratch (allocation-free rule: __device__ globals)
__device__ float g_qp[BATCH * EMB * S_LEN];
__device__ float g_kp[BATCH * EMB * S_LEN];
__device__ float g_vp[BATCH * EMB * S_LEN];
__device__ float g_at[BATCH * EMB * S_LEN];

// ---------------------------------------------------------------------------
// SGEMM with fused bias: C[z] = A(MxK) * B[z](KxN) + bias, all row-major.
// 128x128 block tile, BK=8, 256 threads, 8x8 per thread.
// ---------------------------------------------------------------------------
__global__ __launch_bounds__(256) void sgemm_bias(
    const float* __restrict__ A, const float* __restrict__ bias,
    const float* __restrict__ Bm, float* __restrict__ C,
    int M, int N, int K)
{
    const int BM = 128, BN = 128, BK = 8;
    Bm += (size_t)blockIdx.z * K * N;
    C  += (size_t)blockIdx.z * M * N;

    __shared__ float As[BK][BM];
    __shared__ float Bs[BK][BN];

    const int tid  = threadIdx.x;
    const int m0   = blockIdx.y * BM;
    const int n0   = blockIdx.x * BN;
    const int aRow = tid >> 1;            // 0..127
    const int aCol = (tid & 1) * 4;       // 0 or 4
    const int bRow = tid >> 5;            // 0..7
    const int bCol = (tid & 31) * 4;      // 0..124
    const int tm   = (tid >> 4) * 8;
    const int tn   = (tid & 15) * 8;

    float acc[8][8] = {};

    for (int k0 = 0; k0 < K; k0 += BK) {
        float4 av = *(const float4*)(A + (size_t)(m0 + aRow) * K + k0 + aCol);
        As[aCol + 0][aRow] = av.x;
        As[aCol + 1][aRow] = av.y;
        As[aCol + 2][aRow] = av.z;
        As[aCol + 3][aRow] = av.w;
        *(float4*)(&Bs[bRow][bCol]) =
            *(const float4*)(Bm + (size_t)(k0 + bRow) * N + n0 + bCol);
        __syncthreads();

#pragma unroll
        for (int kk = 0; kk < BK; kk++) {
            float a[8], bb[8];
#pragma unroll
            for (int i = 0; i < 8; i++) a[i] = As[kk][tm + i];
#pragma unroll
            for (int j = 0; j < 8; j++) bb[j] = Bs[kk][tn + j];
#pragma unroll
            for (int i = 0; i < 8; i++)
#pragma unroll
                for (int j = 0; j < 8; j++)
                    acc[i][j] = fmaf(a[i], bb[j], acc[i][j]);
        }
        __syncthreads();
    }

#pragma unroll
    for (int i = 0; i < 8; i++) {
        float bv = bias[m0 + tm + i];
        float* crow = C + (size_t)(m0 + tm + i) * N + n0 + tn;
#pragma unroll
        for (int j = 0; j < 8; j += 4) {
            float4 v = {acc[i][j] + bv, acc[i][j + 1] + bv,
                        acc[i][j + 2] + bv, acc[i][j + 3] + bv};
            *(float4*)(crow + j) = v;
        }
    }
}

// ---------------------------------------------------------------------------
// Flash-style attention, fp32. One block per (q-tile of 64, head, batch).
// Q/K/V layout: [b][h*64+c][s] (s contiguous). mask: [b][k][q].
// scores[k][q] = sum_c Q[c][q]*K[c][k]*scale + mask[k][q]; softmax over k;
// O[c][q] = sum_k P[k][q] * V[c][k].
// ---------------------------------------------------------------------------
__global__ __launch_bounds__(256) void attn_kernel(
    const float* __restrict__ Q, const float* __restrict__ Kp,
    const float* __restrict__ Vp, const float* __restrict__ Mk,
    float* __restrict__ Out)
{
    extern __shared__ float sm[];
    float* Qs   = sm;               // [64][64] (scaled Q, c-major)
    float* KVs  = Qs + 64 * 64;     // [64][64] (K, then V)
    float* Ss   = KVs + 64 * 64;    // [64 k][64 q] scores / probs
    float* red  = Ss + 64 * 64;     // [4][64]
    float* mrow = red + 4 * 64;     // [64] running max
    float* lrow = mrow + 64;        // [64] running sum
    float* arow = lrow + 64;        // [64] rescale factor

    const int tid = threadIdx.x;
    const int tx  = tid & 15;       // q sub-tile
    const int ty  = tid >> 4;       // k / c sub-tile
    const int q0  = blockIdx.x * 64;
    const int h   = blockIdx.y;
    const int b   = blockIdx.z;
    const size_t base = (((size_t)b * NH + h) * DH) * S_LEN;
    const float* mb = Mk + (size_t)b * S_LEN * S_LEN;

    // Load Q tile, fused scale (dh^-0.5 = 0.125)
    for (int i = tid; i < 64 * 16; i += 256) {
        int c  = i >> 4;
        int q4 = (i & 15) << 2;
        float4 v = *(const float4*)(Q + base + (size_t)c * S_LEN + q0 + q4);
        v.x *= 0.125f; v.y *= 0.125f; v.z *= 0.125f; v.w *= 0.125f;
        *(float4*)(Qs + c * 64 + q4) = v;
    }
    if (tid < 64) { mrow[tid] = -1e30f; lrow[tid] = 0.f; }

    float oacc[4][4] = {};
    const int qi = tid & 63;
    const int g  = tid >> 6;

    for (int k0 = 0; k0 < S_LEN; k0 += 64) {
        __syncthreads();  // KVs free (prev GEMM2 done), Qs visible on iter 0
        // Load K tile: KVs[c][k]
        for (int i = tid; i < 64 * 16; i += 256) {
            int c  = i >> 4;
            int k4 = (i & 15) << 2;
            *(float4*)(KVs + c * 64 + k4) =
                *(const float4*)(Kp + base + (size_t)c * S_LEN + k0 + k4);
        }
        __syncthreads();

        // GEMM1: S[k][q] = sum_c K[c][k] * Qscaled[c][q]
        float sacc[4][4] = {};
#pragma unroll 16
        for (int c = 0; c < DH; c++) {
            float kv[4], qv[4];
#pragma unroll
            for (int i = 0; i < 4; i++) kv[i] = KVs[c * 64 + ty * 4 + i];
#pragma unroll
            for (int j = 0; j < 4; j++) qv[j] = Qs[c * 64 + tx * 4 + j];
#pragma unroll
            for (int i = 0; i < 4; i++)
#pragma unroll
                for (int j = 0; j < 4; j++)
                    sacc[i][j] = fmaf(kv[i], qv[j], sacc[i][j]);
        }
        // + mask, store to Ss
#pragma unroll
        for (int i = 0; i < 4; i++) {
            float4 mv = *(const float4*)(mb + (size_t)(k0 + ty * 4 + i) * S_LEN
                                         + q0 + tx * 4);
            float4 sv = {sacc[i][0] + mv.x, sacc[i][1] + mv.y,
                         sacc[i][2] + mv.z, sacc[i][3] + mv.w};
            *(float4*)(Ss + (ty * 4 + i) * 64 + tx * 4) = sv;
        }
        __syncthreads();  // Ss ready; KVs free for V

        // Load V tile into KVs
        for (int i = tid; i < 64 * 16; i += 256) {
            int c  = i >> 4;
            int k4 = (i & 15) << 2;
            *(float4*)(KVs + c * 64 + k4) =
                *(const float4*)(Vp + base + (size_t)c * S_LEN + k0 + k4);
        }
        // Tile max per q column (4 threads per column, 16 rows each)
        float lm = -1e30f;
#pragma unroll
        for (int kk = 0; kk < 16; kk++)
            lm = fmaxf(lm, Ss[(g * 16 + kk) * 64 + qi]);
        red[g * 64 + qi] = lm;
        __syncthreads();

        if (tid < 64) {
            float tmx = fmaxf(fmaxf(red[tid], red[64 + tid]),
                              fmaxf(red[128 + tid], red[192 + tid]));
            float mo = mrow[tid];
            float mn = fmaxf(mo, tmx);
            arow[tid] = __expf(mo - mn);
            mrow[tid] = mn;
        }
        __syncthreads();

        // exp + tile sum
        float mn = mrow[qi];
        float ls = 0.f;
#pragma unroll
        for (int kk = 0; kk < 16; kk++) {
            float p = __expf(Ss[(g * 16 + kk) * 64 + qi] - mn);
            Ss[(g * 16 + kk) * 64 + qi] = p;
            ls += p;
        }
        red[g * 64 + qi] = ls;
        __syncthreads();

        if (tid < 64)
            lrow[tid] = lrow[tid] * arow[tid]
                      + red[tid] + red[64 + tid] + red[128 + tid] + red[192 + tid];

        // Rescale O accumulator, then GEMM2: O[c][q] += V[c][k] * P[k][q]
        float aj[4];
#pragma unroll
        for (int j = 0; j < 4; j++) aj[j] = arow[tx * 4 + j];
#pragma unroll
        for (int i = 0; i < 4; i++)
#pragma unroll
            for (int j = 0; j < 4; j++) oacc[i][j] *= aj[j];

#pragma unroll 16
        for (int kk = 0; kk < 64; kk++) {
            float vv[4], pv[4];
#pragma unroll
            for (int i = 0; i < 4; i++) vv[i] = KVs[(ty * 4 + i) * 64 + kk];
#pragma unroll
            for (int j = 0; j < 4; j++) pv[j] = Ss[kk * 64 + tx * 4 + j];
#pragma unroll
            for (int i = 0; i < 4; i++)
#pragma unroll
                for (int j = 0; j < 4; j++)
                    oacc[i][j] = fmaf(vv[i], pv[j], oacc[i][j]);
        }
    }
    __syncthreads();

    float linv[4];
#pragma unroll
    for (int j = 0; j < 4; j++) linv[j] = 1.f / lrow[tx * 4 + j];
#pragma unroll
    for (int i = 0; i < 4; i++) {
        float4 ov = {oacc[i][0] * linv[0], oacc[i][1] * linv[1],
                     oacc[i][2] * linv[2], oacc[i][3] * linv[3]};
        *(float4*)(Out + base + (size_t)(ty * 4 + i) * S_LEN + q0 + tx * 4) = ov;
    }
}

// ---------------------------------------------------------------------------
extern "C" void kernel_launch(void* const* d_in, const int* in_sizes, int n_in,
                              void* d_out, int out_size)
{
    const float* q    = (const float*)d_in[0];
    const float* k    = (const float*)d_in[1];
    const float* v    = (const float*)d_in[2];
    const float* mask = (const float*)d_in[3];
    const float* Wq   = (const float*)d_in[4];
    const float* bq   = (const float*)d_in[5];
    const float* Wk   = (const float*)d_in[6];
    const float* bk   = (const float*)d_in[7];
    const float* Wv   = (const float*)d_in[8];
    const float* bv   = (const float*)d_in[9];
    const float* Wo   = (const float*)d_in[10];
    const float* bo   = (const float*)d_in[11];
    float* out = (float*)d_out;

    float *qp, *kp, *vp, *at;
    cudaGetSymbolAddress((void**)&qp, g_qp);
    cudaGetSymbolAddress((void**)&kp, g_kp);
    cudaGetSymbolAddress((void**)&vp, g_vp);
    cudaGetSymbolAddress((void**)&at, g_at);

    dim3 gp(S_LEN / 128, EMB / 128, BATCH);  // (16, 8, 2)
    sgemm_bias<<<gp, 256>>>(Wq, bq, q, qp, EMB, S_LEN, EMB);
    sgemm_bias<<<gp, 256>>>(Wk, bk, k, kp, EMB, S_LEN, EMB);
    sgemm_bias<<<gp, 256>>>(Wv, bv, v, vp, EMB, S_LEN, EMB);

    size_t smem = (size_t)(64 * 64 * 3 + 4 * 64 + 3 * 64) * sizeof(float); // 50944 B
    cudaFuncSetAttribute(attn_kernel, cudaFuncAttributeMaxDynamicSharedMemorySize,
                         (int)smem);
    attn_kernel<<<dim3(S_LEN / 64, NH, BATCH), 256, smem>>>(qp, kp, vp, mask, at);

    sgemm_bias<<<gp, 256>>>(Wo, bo, at, out, EMB, S_LEN, EMB);
}

// round 2
// speedup vs baseline: 1.4449x; 1.4449x over previous
#include <cuda_runtime.h>
#include <cstdint>

#define S_LEN 2048
#define EMB   1024
#define BATCH 2
#define NH    16
#define DH    64

// Scratch (allocation-free rule: __device__ globals)
__device__ float g_qp[BATCH * EMB * S_LEN];
__device__ float g_kp[BATCH * EMB * S_LEN];
__device__ float g_vp[BATCH * EMB * S_LEN];
__device__ float g_at[BATCH * EMB * S_LEN];

__device__ __forceinline__ float f2tf(float f) {
    uint32_t u;
    asm("cvt.rna.tf32.f32 %0, %1;" : "=r"(u) : "f"(f));
    return __uint_as_float(u);
}

__device__ __forceinline__ void mma_tf32(float c[4],
    uint32_t a0, uint32_t a1, uint32_t a2, uint32_t a3,
    uint32_t b0, uint32_t b1)
{
    asm volatile(
        "mma.sync.aligned.m16n8k8.row.col.f32.tf32.tf32.f32 "
        "{%0,%1,%2,%3}, {%4,%5,%6,%7}, {%8,%9}, {%0,%1,%2,%3};"
        : "+f"(c[0]), "+f"(c[1]), "+f"(c[2]), "+f"(c[3])
        : "r"(a0), "r"(a1), "r"(a2), "r"(a3), "r"(b0), "r"(b1));
}

__device__ __forceinline__ uint32_t F2U(float f) { return __float_as_uint(f); }

// ---------------------------------------------------------------------------
// TF32 tensor-core GEMM with fused bias: C[z] = A(1024x1024) * B[z](1024x2048)
// + bias. 128x128 block, BK=16, 8 warps (2x4), warp tile 64x32, m16n8k8 mma.
// ---------------------------------------------------------------------------
__global__ __launch_bounds__(256) void gemm_tf32_bias(
    const float* __restrict__ A, const float* __restrict__ bias,
    const float* __restrict__ Bm, float* __restrict__ C)
{
    const int K = EMB, N = S_LEN;
    Bm += (size_t)blockIdx.z * K * N;
    C  += (size_t)blockIdx.z * EMB * N;

    __shared__ float As[128][20];   // stride 20 -> conflict-free A-frag reads
    __shared__ float Bs[16][136];   // stride 136 -> conflict-free B-frag reads

    const int tid  = threadIdx.x;
    const int lane = tid & 31;
    const int w    = tid >> 5;
    const int g    = lane >> 2;   // group id (0..7)
    const int t    = lane & 3;    // thread-in-group (0..3)
    const int wm   = (w >> 2) * 64;
    const int wn   = (w & 3) * 32;
    const int m0   = blockIdx.y * 128;
    const int n0   = blockIdx.x * 128;

    const int arow = tid >> 1, acol = (tid & 1) * 8;
    const int brow = tid >> 4, bcol = (tid & 15) * 8;

    float acc[4][4][4] = {};

    float4 aR[2], bR[2];
    {
        const float* ap = A + (size_t)(m0 + arow) * K + acol;
        aR[0] = *(const float4*)ap;
        aR[1] = *(const float4*)(ap + 4);
        const float* bp = Bm + (size_t)brow * N + n0 + bcol;
        bR[0] = *(const float4*)bp;
        bR[1] = *(const float4*)(bp + 4);
    }

    for (int k0 = 0; k0 < K; k0 += 16) {
        // store prefetched tile to smem (tf32-rounded)
#pragma unroll
        for (int i = 0; i < 2; i++) {
            float4 v = aR[i];
            float4 cv = {f2tf(v.x), f2tf(v.y), f2tf(v.z), f2tf(v.w)};
            *(float4*)(&As[arow][acol + i * 4]) = cv;
            v = bR[i];
            float4 cw = {f2tf(v.x), f2tf(v.y), f2tf(v.z), f2tf(v.w)};
            *(float4*)(&Bs[brow][bcol + i * 4]) = cw;
        }
        __syncthreads();

        if (k0 + 16 < K) {
            const float* ap = A + (size_t)(m0 + arow) * K + k0 + 16 + acol;
            aR[0] = *(const float4*)ap;
            aR[1] = *(const float4*)(ap + 4);
            const float* bp = Bm + (size_t)(k0 + 16 + brow) * N + n0 + bcol;
            bR[0] = *(const float4*)bp;
            bR[1] = *(const float4*)(bp + 4);
        }

#pragma unroll
        for (int ks = 0; ks < 16; ks += 8) {
            uint32_t af[4][4];
#pragma unroll
            for (int mf = 0; mf < 4; mf++) {
                int r = wm + mf * 16;
                af[mf][0] = F2U(As[r + g    ][ks + t    ]);
                af[mf][1] = F2U(As[r + g + 8][ks + t    ]);
                af[mf][2] = F2U(As[r + g    ][ks + t + 4]);
                af[mf][3] = F2U(As[r + g + 8][ks + t + 4]);
            }
            uint32_t bf[4][2];
#pragma unroll
            for (int nf = 0; nf < 4; nf++) {
                int cc = wn + nf * 8 + g;
                bf[nf][0] = F2U(Bs[ks + t    ][cc]);
                bf[nf][1] = F2U(Bs[ks + t + 4][cc]);
            }
#pragma unroll
            for (int mf = 0; mf < 4; mf++)
#pragma unroll
                for (int nf = 0; nf < 4; nf++)
                    mma_tf32(acc[mf][nf], af[mf][0], af[mf][1], af[mf][2],
                             af[mf][3], bf[nf][0], bf[nf][1]);
        }
        __syncthreads();
    }

#pragma unroll
    for (int mf = 0; mf < 4; mf++) {
        int r0 = m0 + wm + mf * 16 + g;
        float bv0 = bias[r0], bv1 = bias[r0 + 8];
#pragma unroll
        for (int nf = 0; nf < 4; nf++) {
            int cc = n0 + wn + nf * 8 + 2 * t;
            float2 v0 = {acc[mf][nf][0] + bv0, acc[mf][nf][1] + bv0};
            float2 v1 = {acc[mf][nf][2] + bv1, acc[mf][nf][3] + bv1};
            *(float2*)(C + (size_t)r0 * N + cc)       = v0;
            *(float2*)(C + (size_t)(r0 + 8) * N + cc) = v1;
        }
    }
}

// ---------------------------------------------------------------------------
// Flash attention, tf32 tensor cores. Block = (64 q) x (head) x (batch),
// 4 warps; warp w owns q rows [16w, 16w+16). Softmax rows live within a warp.
// ---------------------------------------------------------------------------
__global__ __launch_bounds__(128) void attn_tf32(
    const float* __restrict__ Q, const float* __restrict__ Kp,
    const float* __restrict__ Vp, const float* __restrict__ Mk,
    float* __restrict__ Out)
{
    extern __shared__ float sm[];
    float* Qs = sm;                 // [64 c][72]  (q cols)
    float* Ks = Qs + 64 * 72;       // [64 c][72]  (k cols)
    float* Vs = Ks + 64 * 72;       // [64 c][68]  (k cols)
    float* Ms = Vs + 64 * 68;       // [64 k][68]  (q cols), fp32 mask
    float* Ps = Ms + 64 * 68;       // [64 q][68]  (k cols) probs / O staging

    const int tid  = threadIdx.x;
    const int lane = tid & 31;
    const int w    = tid >> 5;
    const int g    = lane >> 2;
    const int t    = lane & 3;
    const int wq   = w * 16;
    const int q0   = blockIdx.x * 64;
    const int h    = blockIdx.y;
    const int b    = blockIdx.z;
    const size_t base = (((size_t)b * NH + h) * DH) * S_LEN;
    const float* mb = Mk + (size_t)b * S_LEN * S_LEN;

    const int lr = tid >> 1;            // 0..63 row
    const int lc = (tid & 1) * 32;      // col segment

    // Q tile (scaled, tf32-rounded)
    {
        const float* p = Q + base + (size_t)lr * S_LEN + q0 + lc;
#pragma unroll
        for (int j = 0; j < 32; j += 4) {
            float4 v = *(const float4*)(p + j);
            float4 cv = {f2tf(v.x * 0.125f), f2tf(v.y * 0.125f),
                         f2tf(v.z * 0.125f), f2tf(v.w * 0.125f)};
            *(float4*)(Qs + lr * 72 + lc + j) = cv;
        }
    }

    float of[8][4] = {};
    float m_g = -1e30f, m_g8 = -1e30f, l_g = 0.f, l_g8 = 0.f;

    for (int k0 = 0; k0 < S_LEN; k0 += 64) {
        __syncthreads();
        // K, V (tf32), mask (fp32) tiles
        {
            const float* p = Kp + base + (size_t)lr * S_LEN + k0 + lc;
#pragma unroll
            for (int j = 0; j < 32; j += 4) {
                float4 v = *(const float4*)(p + j);
                float4 cv = {f2tf(v.x), f2tf(v.y), f2tf(v.z), f2tf(v.w)};
                *(float4*)(Ks + lr * 72 + lc + j) = cv;
            }
            p = Vp + base + (size_t)lr * S_LEN + k0 + lc;
#pragma unroll
            for (int j = 0; j < 32; j += 4) {
                float4 v = *(const float4*)(p + j);
                float4 cv = {f2tf(v.x), f2tf(v.y), f2tf(v.z), f2tf(v.w)};
                *(float4*)(Vs + lr * 68 + lc + j) = cv;
            }
            p = mb + (size_t)(k0 + lr) * S_LEN + q0 + lc;
#pragma unroll
            for (int j = 0; j < 32; j += 4)
                *(float4*)(Ms + lr * 68 + lc + j) = *(const float4*)(p + j);
        }
        __syncthreads();

        // GEMM1: S[q][k] = sum_c Qhat[q][c] * K[c][k]
        float sf[8][4] = {};
#pragma unroll
        for (int kc = 0; kc < DH; kc += 8) {
            uint32_t a0 = F2U(Qs[(kc + t)     * 72 + wq + g]);
            uint32_t a1 = F2U(Qs[(kc + t)     * 72 + wq + g + 8]);
            uint32_t a2 = F2U(Qs[(kc + t + 4) * 72 + wq + g]);
            uint32_t a3 = F2U(Qs[(kc + t + 4) * 72 + wq + g + 8]);
#pragma unroll
            for (int nf = 0; nf < 8; nf++) {
                uint32_t b0 = F2U(Ks[(kc + t)     * 72 + nf * 8 + g]);
                uint32_t b1 = F2U(Ks[(kc + t + 4) * 72 + nf * 8 + g]);
                mma_tf32(sf[nf], a0, a1, a2, a3, b0, b1);
            }
        }
        // + mask
#pragma unroll
        for (int nf = 0; nf < 8; nf++) {
            int kc = nf * 8 + 2 * t;
            sf[nf][0] += Ms[kc * 68 + wq + g];
            sf[nf][1] += Ms[(kc + 1) * 68 + wq + g];
            sf[nf][2] += Ms[kc * 68 + wq + g + 8];
            sf[nf][3] += Ms[(kc + 1) * 68 + wq + g + 8];
        }
        // row max (rows wq+g, wq+g+8) across 64 k
        float mx0 = -1e30f, mx8 = -1e30f;
#pragma unroll
        for (int nf = 0; nf < 8; nf++) {
            mx0 = fmaxf(mx0, fmaxf(sf[nf][0], sf[nf][1]));
            mx8 = fmaxf(mx8, fmaxf(sf[nf][2], sf[nf][3]));
        }
        mx0 = fmaxf(mx0, __shfl_xor_sync(0xffffffffu, mx0, 1));
        mx0 = fmaxf(mx0, __shfl_xor_sync(0xffffffffu, mx0, 2));
        mx8 = fmaxf(mx8, __shfl_xor_sync(0xffffffffu, mx8, 1));
        mx8 = fmaxf(mx8, __shfl_xor_sync(0xffffffffu, mx8, 2));

        float mn0 = fmaxf(m_g, mx0),  mn8 = fmaxf(m_g8, mx8);
        float al0 = __expf(m_g - mn0), al8 = __expf(m_g8 - mn8);
        m_g = mn0; m_g8 = mn8;

        float s0 = 0.f, s8 = 0.f;
#pragma unroll
        for (int nf = 0; nf < 8; nf++) {
            sf[nf][0] = __expf(sf[nf][0] - mn0);
            sf[nf][1] = __expf(sf[nf][1] - mn0);
            sf[nf][2] = __expf(sf[nf][2] - mn8);
            sf[nf][3] = __expf(sf[nf][3] - mn8);
            s0 += sf[nf][0] + sf[nf][1];
            s8 += sf[nf][2] + sf[nf][3];
        }
        s0 += __shfl_xor_sync(0xffffffffu, s0, 1);
        s0 += __shfl_xor_sync(0xffffffffu, s0, 2);
        s8 += __shfl_xor_sync(0xffffffffu, s8, 1);
        s8 += __shfl_xor_sync(0xffffffffu, s8, 2);
        l_g  = l_g  * al0 + s0;
        l_g8 = l_g8 * al8 + s8;

        // rescale O, stage P to smem (tf32)
#pragma unroll
        for (int nf = 0; nf < 8; nf++) {
            of[nf][0] *= al0; of[nf][1] *= al0;
            of[nf][2] *= al8; of[nf][3] *= al8;
            int kc = nf * 8 + 2 * t;
            Ps[(wq + g)     * 68 + kc]     = f2tf(sf[nf][0]);
            Ps[(wq + g)     * 68 + kc + 1] = f2tf(sf[nf][1]);
            Ps[(wq + g + 8) * 68 + kc]     = f2tf(sf[nf][2]);
            Ps[(wq + g + 8) * 68 + kc + 1] = f2tf(sf[nf][3]);
        }
        __syncthreads();

        // GEMM2: O[q][c] += sum_k P[q][k] * V[c][k]
#pragma unroll
        for (int ks = 0; ks < 64; ks += 8) {
            uint32_t a0 = F2U(Ps[(wq + g)     * 68 + ks + t]);
            uint32_t a1 = F2U(Ps[(wq + g + 8) * 68 + ks + t]);
            uint32_t a2 = F2U(Ps[(wq + g)     * 68 + ks + t + 4]);
            uint32_t a3 = F2U(Ps[(wq + g + 8) * 68 + ks + t + 4]);
#pragma unroll
            for (int nf = 0; nf < 8; nf++) {
                uint32_t b0 = F2U(Vs[(nf * 8 + g) * 68 + ks + t]);
                uint32_t b1 = F2U(Vs[(nf * 8 + g) * 68 + ks + t + 4]);
                mma_tf32(of[nf], a0, a1, a2, a3, b0, b1);
            }
        }
    }
    __syncthreads();

    // normalize + transpose via Ps, write Out[c][q] coalesced
    float il0 = 1.f / l_g, il8 = 1.f / l_g8;
#pragma unroll
    for (int nf = 0; nf < 8; nf++) {
        int cc = nf * 8 + 2 * t;
        Ps[(wq + g)     * 68 + cc]     = of[nf][0] * il0;
        Ps[(wq + g)     * 68 + cc + 1] = of[nf][1] * il0;
        Ps[(wq + g + 8) * 68 + cc]     = of[nf][2] * il8;
        Ps[(wq + g + 8) * 68 + cc + 1] = of[nf][3] * il8;
    }
    __syncthreads();
    {
        float* op = Out + base + (size_t)lr * S_LEN + q0 + lc;  // row c = lr
#pragma unroll
        for (int j = 0; j < 32; j += 4) {
            float4 v = {Ps[(lc + j)     * 68 + lr], Ps[(lc + j + 1) * 68 + lr],
                        Ps[(lc + j + 2) * 68 + lr], Ps[(lc + j + 3) * 68 + lr]};
            *(float4*)(op + j) = v;
        }
    }
}

// ---------------------------------------------------------------------------
extern "C" void kernel_launch(void* const* d_in, const int* in_sizes, int n_in,
                              void* d_out, int out_size)
{
    const float* q    = (const float*)d_in[0];
    const float* k    = (const float*)d_in[1];
    const float* v    = (const float*)d_in[2];
    const float* mask = (const float*)d_in[3];
    const float* Wq   = (const float*)d_in[4];
    const float* bq   = (const float*)d_in[5];
    const float* Wk   = (const float*)d_in[6];
    const float* bk   = (const float*)d_in[7];
    const float* Wv   = (const float*)d_in[8];
    const float* bv   = (const float*)d_in[9];
    const float* Wo   = (const float*)d_in[10];
    const float* bo   = (const float*)d_in[11];
    float* out = (float*)d_out;

    float *qp, *kp, *vp, *at;
    cudaGetSymbolAddress((void**)&qp, g_qp);
    cudaGetSymbolAddress((void**)&kp, g_kp);
    cudaGetSymbolAddress((void**)&vp, g_vp);
    cudaGetSymbolAddress((void**)&at, g_at);

    dim3 gp(S_LEN / 128, EMB / 128, BATCH);  // (16, 8, 2)
    gemm_tf32_bias<<<gp, 256>>>(Wq, bq, q, qp);
    gemm_tf32_bias<<<gp, 256>>>(Wk, bk, k, kp);
    gemm_tf32_bias<<<gp, 256>>>(Wv, bv, v, vp);

    size_t smem = (size_t)(64 * 72 * 2 + 64 * 68 * 3) * sizeof(float); // 89088
    static int attr_set = 0;
    cudaFuncSetAttribute(attn_tf32, cudaFuncAttributeMaxDynamicSharedMemorySize,
                         (int)smem);
    (void)attr_set;
    attn_tf32<<<dim3(S_LEN / 64, NH, BATCH), 128, smem>>>(qp, kp, vp, mask, at);

    gemm_tf32_bias<<<gp, 256>>>(Wo, bo, at, out);
}